// round 6
// baseline (speedup 1.0000x reference)
#include <cuda_runtime.h>
#include <cuda_bf16.h>
#include <cstdint>
#include <math.h>

#define BB 4096
#define LL 50
#define DD 64

constexpr int ROWS_TOT = BB * LL;        // 204800
constexpr int NT16     = ROWS_TOT / 16;  // 12800 warp-tiles of 16 rows
constexpr int THR      = 256;            // 8 warps / block

// ---- mlp smem layout ----
constexpr int OFF_WS = 0;                // 5 layers x (hi 8192 + lo 8192)
constexpr int FBASE  = 81920;
constexpr int F_BG1 = 0, F_BG2 = 64, F_BG3 = 128, F_BA1 = 192, F_BA2 = 256;
constexpr int F_W3 = 320, F_BA3 = 384, F_ER = 448;
constexpr int SMEM_SZ = FBASE + (448 + 320) * 4;   // 84992 B

// device scratch
__device__ float g_scores[ROWS_TOT];
__device__ float g_fjt[ROWS_TOT * DD];
__device__ float g_qc[BB * DD];
__device__ float g_er[5 * DD];

// ===================== helpers =====================
__device__ __forceinline__ uint32_t cvt2(float v_lo, float v_hi) {
    uint32_t r;
    asm("cvt.rn.bf16x2.f32 %0, %1, %2;" : "=r"(r) : "f"(v_hi), "f"(v_lo));
    return r;
}
__device__ __forceinline__ float blo(uint32_t p) { return __uint_as_float(p << 16); }
__device__ __forceinline__ float bhi(uint32_t p) { return __uint_as_float(p & 0xffff0000u); }
__device__ __forceinline__ void split2(float v0, float v1, uint32_t& h, uint32_t& l) {
    h = cvt2(v0, v1);
    l = cvt2(v0 - blo(h), v1 - bhi(h));
}
__device__ __forceinline__ void mma(float* d, const uint32_t* a, uint32_t b0, uint32_t b1) {
    asm volatile(
        "mma.sync.aligned.m16n8k16.row.col.f32.bf16.bf16.f32 "
        "{%0,%1,%2,%3}, {%4,%5,%6,%7}, {%8,%9}, {%0,%1,%2,%3};"
        : "+f"(d[0]), "+f"(d[1]), "+f"(d[2]), "+f"(d[3])
        : "r"(a[0]), "r"(a[1]), "r"(a[2]), "r"(a[3]), "r"(b0), "r"(b1));
}

// PASSES==3: hh + hl + lh (split-bf16, ~2^-16 product error). PASSES==1: hh only.
template<int PASSES>
__device__ __forceinline__ void run_layer(const char* ws, int lay,
        const uint32_t (&Ahi)[4][4], const uint32_t (&Alo)[4][4], float (&D)[8][4], int lane) {
#pragma unroll
    for (int nt = 0; nt < 8; nt++) { D[nt][0] = 0.f; D[nt][1] = 0.f; D[nt][2] = 0.f; D[nt][3] = 0.f; }
    const char* base = ws + lay * 16384 + lane * 8;
#pragma unroll
    for (int kt = 0; kt < 4; kt++) {
#pragma unroll
        for (int nt = 0; nt < 8; nt++) {
            const char* p = base + (kt * 8 + nt) * 256;
            uint2 bh = *reinterpret_cast<const uint2*>(p);
            mma(D[nt], Ahi[kt], bh.x, bh.y);
            if (PASSES == 3) {
                uint2 bl = *reinterpret_cast<const uint2*>(p + 8192);
                mma(D[nt], Ahi[kt], bl.x, bl.y);
                mma(D[nt], Alo[kt], bh.x, bh.y);
            }
        }
    }
}

// Epilogue: bias (+extra) (+relu) (+store), D-frags -> next A-frags (hi, and lo if LO).
template<bool RELU, bool EX, bool SG, bool LO>
__device__ __forceinline__ void epilogue(float (&D)[8][4], uint32_t (&Ahi)[4][4], uint32_t (&Alo)[4][4],
        const float* bias, const float* e0, const float* e1, float* g0, float* g1, int tig) {
#pragma unroll
    for (int nt = 0; nt < 8; nt++) {
        int col = nt * 8 + 2 * tig;
        float2 bc = *reinterpret_cast<const float2*>(bias + col);
        float v0 = D[nt][0] + bc.x, v1 = D[nt][1] + bc.y;
        float v2 = D[nt][2] + bc.x, v3 = D[nt][3] + bc.y;
        if (EX) {
            float2 ea = *reinterpret_cast<const float2*>(e0 + col);
            float2 eb = *reinterpret_cast<const float2*>(e1 + col);
            v0 += ea.x; v1 += ea.y; v2 += eb.x; v3 += eb.y;
        }
        if (RELU) {
            v0 = fmaxf(v0, 0.f); v1 = fmaxf(v1, 0.f);
            v2 = fmaxf(v2, 0.f); v3 = fmaxf(v3, 0.f);
        }
        if (SG) {
            *reinterpret_cast<float2*>(g0 + col) = make_float2(v0, v1);
            *reinterpret_cast<float2*>(g1 + col) = make_float2(v2, v3);
        }
        int kt = nt >> 1, ix = (nt & 1) * 2;
        if (LO) {
            split2(v0, v1, Ahi[kt][ix],     Alo[kt][ix]);
            split2(v2, v3, Ahi[kt][ix + 1], Alo[kt][ix + 1]);
        } else {
            Ahi[kt][ix]     = cvt2(v0, v1);
            Ahi[kt][ix + 1] = cvt2(v2, v3);
        }
    }
}

// ===================== prep v2: er_proj + qc (weights staged in smem) =====================
constexpr int QB = 32;   // b's per block
__global__ void __launch_bounds__(256) prep_kernel(
    const int* __restrict__ nodes_v, const float* __restrict__ embed_i,
    const float* __restrict__ embed_r, const float* __restrict__ gv_w1,
    const float* __restrict__ att_w1) {
    int tid = threadIdx.x;
    if (blockIdx.x == 0) {
        for (int e = tid; e < 320; e += 256) {
            int r = e >> 6, j = e & 63;
            float s = 0.f;
#pragma unroll 8
            for (int k = 0; k < 64; k++) s += embed_r[r * 64 + k] * gv_w1[(64 + k) * 64 + j];
            g_er[e] = s;
        }
        return;
    }
    __shared__ float W[64 * 64];    // att_w1 rows 64..127
    __shared__ float Q[QB][64];
    int b0 = (blockIdx.x - 1) * QB;
    for (int e = tid; e < 4096; e += 256) W[e] = att_w1[64 * 64 + e];
    for (int e = tid; e < QB * 64; e += 256) {
        int bl = e >> 6, k = e & 63;
        Q[bl][k] = embed_i[(size_t)nodes_v[b0 + bl] * 64 + k];
    }
    __syncthreads();
    int j = tid & 63, r0 = tid >> 6;
    for (int bl = r0; bl < QB; bl += 4) {
        float s = 0.f;
#pragma unroll 8
        for (int k = 0; k < 64; k++) s += Q[bl][k] * W[k * 64 + j];
        g_qc[(size_t)(b0 + bl) * 64 + j] = s;
    }
}

// ===================== HMMA MLP kernel =====================
__global__ void __launch_bounds__(THR, 2) mlp_mma_kernel(
    const int* __restrict__ neigh_u, const int* __restrict__ neigh_r,
    const float* __restrict__ embed_u,
    const float* __restrict__ gv_w1, const float* __restrict__ gv_b1,
    const float* __restrict__ gv_w2, const float* __restrict__ gv_b2,
    const float* __restrict__ gv_w3, const float* __restrict__ gv_b3,
    const float* __restrict__ att_w1, const float* __restrict__ att_b1,
    const float* __restrict__ att_w2, const float* __restrict__ att_b2,
    const float* __restrict__ att_w3, const float* __restrict__ att_b3) {
    extern __shared__ char smem[];
    float* smf = reinterpret_cast<float*>(smem + FBASE);
    int tid = threadIdx.x;

    {   // prepack weights into B-fragment order (hi/lo bf16)
        const float* srcs[5] = {gv_w1, gv_w2, gv_w3, att_w1, att_w2};
        for (int e = tid; e < 5 * 4 * 8 * 32; e += THR) {
            int lay = e >> 10;
            int rem = e & 1023;
            int kt = rem >> 8;
            int rem2 = rem & 255;
            int nt = rem2 >> 5;
            int th = rem2 & 31;
            int tg = th & 3, gn = th >> 2;
            int k0 = kt * 16 + tg * 2, n = nt * 8 + gn;
            const float* w = srcs[lay];
            uint32_t h0, l0, h1, l1;
            split2(w[k0 * 64 + n],       w[(k0 + 1) * 64 + n], h0, l0);
            split2(w[(k0 + 8) * 64 + n], w[(k0 + 9) * 64 + n], h1, l1);
            char* p = smem + OFF_WS + lay * 16384 + (kt * 8 + nt) * 256 + th * 8;
            *reinterpret_cast<uint2*>(p)        = make_uint2(h0, h1);
            *reinterpret_cast<uint2*>(p + 8192) = make_uint2(l0, l1);
        }
    }
    if (tid < 64) {
        smf[F_BG1 + tid] = gv_b1[tid];
        smf[F_BG2 + tid] = gv_b2[tid];
        smf[F_BG3 + tid] = gv_b3[tid];
        smf[F_BA1 + tid] = att_b1[tid];
        smf[F_BA2 + tid] = att_b2[tid];
        smf[F_W3 + tid]  = att_w3[tid];
    }
    for (int e = tid; e < 320; e += THR) smf[F_ER + e] = g_er[e];
    if (tid == 0) smf[F_BA3] = att_b3[0];
    __syncthreads();

    const char* ws = smem + OFF_WS;
    int lane = tid & 31;
    int tig = lane & 3, gid = lane >> 2;
    int gw = blockIdx.x * (THR / 32) + (tid >> 5);
    int stride = gridDim.x * (THR / 32);

    uint32_t Ahi[4][4], Alo[4][4];
    float D[8][4];

    for (int t = gw; t < NT16; t += stride) {
        int grow0 = t * 16 + gid, grow1 = grow0 + 8;
        int nu0 = neigh_u[grow0], nu1 = neigh_u[grow1];
        int nr0 = neigh_r[grow0], nr1 = neigh_r[grow1];
        int b0 = (int)((unsigned)grow0 / 50u), b1 = (int)((unsigned)grow1 / 50u);

        const float* p0 = embed_u + (size_t)nu0 * 64 + 2 * tig;
        const float* p1 = embed_u + (size_t)nu1 * 64 + 2 * tig;
#pragma unroll
        for (int kt = 0; kt < 4; kt++) {
            float2 x0 = *reinterpret_cast<const float2*>(p0 + kt * 16);
            float2 x1 = *reinterpret_cast<const float2*>(p1 + kt * 16);
            float2 x2 = *reinterpret_cast<const float2*>(p0 + kt * 16 + 8);
            float2 x3 = *reinterpret_cast<const float2*>(p1 + kt * 16 + 8);
            split2(x0.x, x0.y, Ahi[kt][0], Alo[kt][0]);
            split2(x1.x, x1.y, Ahi[kt][1], Alo[kt][1]);
            split2(x2.x, x2.y, Ahi[kt][2], Alo[kt][2]);
            split2(x3.x, x3.y, Ahi[kt][3], Alo[kt][3]);
        }

        // L1-L3: full precision (feeds fjt/output)
        run_layer<3>(ws, 0, Ahi, Alo, D, lane);
        epilogue<true, true, false, true>(D, Ahi, Alo, smf + F_BG1,
                                          smf + F_ER + nr0 * 64, smf + F_ER + nr1 * 64,
                                          nullptr, nullptr, tig);
        run_layer<3>(ws, 1, Ahi, Alo, D, lane);
        epilogue<true, false, false, true>(D, Ahi, Alo, smf + F_BG2,
                                           nullptr, nullptr, nullptr, nullptr, tig);
        run_layer<3>(ws, 2, Ahi, Alo, D, lane);
        epilogue<false, false, true, false>(D, Ahi, Alo, smf + F_BG3,
                                            nullptr, nullptr,
                                            g_fjt + (size_t)grow0 * 64, g_fjt + (size_t)grow1 * 64, tig);
        // L4-L5: scores only -> single-pass bf16 is plenty
        run_layer<1>(ws, 3, Ahi, Alo, D, lane);
        epilogue<true, true, false, false>(D, Ahi, Alo, smf + F_BA1,
                                           g_qc + (size_t)b0 * 64, g_qc + (size_t)b1 * 64,
                                           nullptr, nullptr, tig);
        run_layer<1>(ws, 4, Ahi, Alo, D, lane);
        {
            float s0 = 0.f, s1 = 0.f;
            float ba3v = smf[F_BA3];
#pragma unroll
            for (int nt = 0; nt < 8; nt++) {
                int col = nt * 8 + 2 * tig;
                float2 bc = *reinterpret_cast<const float2*>(smf + F_BA2 + col);
                float2 wc = *reinterpret_cast<const float2*>(smf + F_W3 + col);
                s0 += fmaxf(D[nt][0] + bc.x, 0.f) * wc.x + fmaxf(D[nt][1] + bc.y, 0.f) * wc.y;
                s1 += fmaxf(D[nt][2] + bc.x, 0.f) * wc.x + fmaxf(D[nt][3] + bc.y, 0.f) * wc.y;
            }
            s0 += __shfl_xor_sync(0xffffffffu, s0, 1);
            s0 += __shfl_xor_sync(0xffffffffu, s0, 2);
            s1 += __shfl_xor_sync(0xffffffffu, s1, 1);
            s1 += __shfl_xor_sync(0xffffffffu, s1, 2);
            if (tig == 0) {
                g_scores[grow0] = s0 + ba3v;
                g_scores[grow1] = s1 + ba3v;
            }
        }
    }
}

// ===================== combine v2: 16 b's per block, weights in smem =====================
__global__ void __launch_bounds__(256) combine_kernel(
    const int* __restrict__ nodes_v, const float* __restrict__ embed_i,
    const float* __restrict__ wr1_w, const float* __restrict__ wr1_b,
    const float* __restrict__ wr2_w, const float* __restrict__ wr2_b,
    float* __restrict__ out) {
    __shared__ float w1s[128 * 64];
    __shared__ float w2s[64 * 64];
    __shared__ float b1s[64], b2s[64];
    __shared__ float sc[4][64];
    __shared__ float mu[4][64];
    __shared__ float zq[4][128];
    __shared__ float zz[4][64];

    int tid = threadIdx.x;
    int sub = tid >> 6, st = tid & 63;

    for (int e = tid; e < 128 * 64; e += 256) w1s[e] = wr1_w[e];
    for (int e = tid; e < 64 * 64; e += 256) w2s[e] = wr2_w[e];
    if (tid < 64) { b1s[tid] = wr1_b[tid]; b2s[tid] = wr2_b[tid]; }
    __syncthreads();

    for (int g = 0; g < 4; g++) {
        int b = blockIdx.x * 16 + sub * 4 + g;

        sc[sub][st] = (st < LL) ? g_scores[b * LL + st] : -1e30f;
        __syncthreads();

        float mx = -1e30f;
#pragma unroll 10
        for (int l = 0; l < LL; l++) mx = fmaxf(mx, sc[sub][l]);
        float ev = (st < LL) ? __expf(sc[sub][st] - mx) : 0.f;
        mu[sub][st] = ev;
        __syncthreads();

        float den = 0.f;
#pragma unroll 10
        for (int l = 0; l < LL; l++) den += mu[sub][l];
        float acc = 0.f;
        const float* fb = g_fjt + (size_t)(b * LL) * 64 + st;
#pragma unroll 10
        for (int l = 0; l < LL; l++) acc += mu[sub][l] * fb[l * 64];
        zq[sub][st] = acc / den;
        zq[sub][64 + st] = embed_i[(size_t)nodes_v[b] * 64 + st];
        __syncthreads();

        float a1 = b1s[st];
#pragma unroll 16
        for (int k = 0; k < 128; k++) a1 += zq[sub][k] * w1s[k * 64 + st];
        zz[sub][st] = fmaxf(a1, 0.f);
        __syncthreads();

        float a2 = b2s[st];
#pragma unroll 16
        for (int k = 0; k < 64; k++) a2 += zz[sub][k] * w2s[k * 64 + st];
        out[b * 64 + st] = fmaxf(a2, 0.f);
        __syncthreads();
    }
}

extern "C" void kernel_launch(void* const* d_in, const int* in_sizes, int n_in,
                              void* d_out, int out_size) {
    const int*   nodes_v = (const int*)d_in[0];
    const int*   neigh_u = (const int*)d_in[1];
    const int*   neigh_r = (const int*)d_in[2];
    const float* embed_u = (const float*)d_in[3];
    const float* embed_i = (const float*)d_in[4];
    const float* embed_r = (const float*)d_in[5];
    const float* gv_w1  = (const float*)d_in[6];
    const float* gv_b1  = (const float*)d_in[7];
    const float* gv_w2  = (const float*)d_in[8];
    const float* gv_b2  = (const float*)d_in[9];
    const float* gv_w3  = (const float*)d_in[10];
    const float* gv_b3  = (const float*)d_in[11];
    const float* att_w1 = (const float*)d_in[12];
    const float* att_b1 = (const float*)d_in[13];
    const float* att_w2 = (const float*)d_in[14];
    const float* att_b2 = (const float*)d_in[15];
    const float* att_w3 = (const float*)d_in[16];
    const float* att_b3 = (const float*)d_in[17];
    const float* wr1_w  = (const float*)d_in[18];
    const float* wr1_b  = (const float*)d_in[19];
    const float* wr2_w  = (const float*)d_in[20];
    const float* wr2_b  = (const float*)d_in[21];
    float* out = (float*)d_out;

    cudaFuncSetAttribute(mlp_mma_kernel, cudaFuncAttributeMaxDynamicSharedMemorySize, SMEM_SZ);

    int smCount = 148;
    cudaDeviceGetAttribute(&smCount, cudaDevAttrMultiProcessorCount, 0);

    prep_kernel<<<1 + BB / QB, 256>>>(nodes_v, embed_i, embed_r, gv_w1, att_w1);

    mlp_mma_kernel<<<2 * smCount, THR, SMEM_SZ>>>(
        neigh_u, neigh_r, embed_u,
        gv_w1, gv_b1, gv_w2, gv_b2, gv_w3, gv_b3,
        att_w1, att_b1, att_w2, att_b2, att_w3, att_b3);

    combine_kernel<<<BB / 16, 256>>>(nodes_v, embed_i, wr1_w, wr1_b, wr2_w, wr2_b, out);
}

// round 7
// speedup vs baseline: 1.1370x; 1.1370x over previous
#include <cuda_runtime.h>
#include <cuda_bf16.h>
#include <cstdint>
#include <math.h>

#define BB 4096
#define LL 50
#define DD 64

constexpr int ROWS_TOT = BB * LL;        // 204800
constexpr int NT16     = ROWS_TOT / 16;  // 12800 warp-tiles
constexpr int THR      = 256;

// ---- mlp smem layout (bytes) ----
// gv1,gv2,gv3: 16384 each (hi 8192 + lo 8192); att1 hi-only KT=8: 16384; att2 hi-only: 8192
constexpr int L_GV1  = 0;
constexpr int L_GV2  = 16384;
constexpr int L_GV3  = 32768;
constexpr int L_ATT1 = 49152;
constexpr int L_ATT2 = 65536;
constexpr int FBASE  = 73728;
constexpr int F_BG1 = 0, F_BG2 = 64, F_BG3 = 128, F_BA1 = 192, F_BA2 = 256;
constexpr int F_W3 = 320, F_BA3 = 384, F_ER = 448;      // er: 5*64 -> 448..768
constexpr int SMEM_SZ = FBASE + 768 * 4;                 // 76800 B

// device scratch
__device__ float g_scores[ROWS_TOT];
__device__ float g_fjt[ROWS_TOT * DD];

// ===================== helpers =====================
__device__ __forceinline__ uint32_t cvt2(float v_lo, float v_hi) {
    uint32_t r;
    asm("cvt.rn.bf16x2.f32 %0, %1, %2;" : "=r"(r) : "f"(v_hi), "f"(v_lo));
    return r;
}
__device__ __forceinline__ float blo(uint32_t p) { return __uint_as_float(p << 16); }
__device__ __forceinline__ float bhi(uint32_t p) { return __uint_as_float(p & 0xffff0000u); }
__device__ __forceinline__ void split2(float v0, float v1, uint32_t& h, uint32_t& l) {
    h = cvt2(v0, v1);
    l = cvt2(v0 - blo(h), v1 - bhi(h));
}
__device__ __forceinline__ void mma(float* d, const uint32_t* a, uint32_t b0, uint32_t b1) {
    asm volatile(
        "mma.sync.aligned.m16n8k16.row.col.f32.bf16.bf16.f32 "
        "{%0,%1,%2,%3}, {%4,%5,%6,%7}, {%8,%9}, {%0,%1,%2,%3};"
        : "+f"(d[0]), "+f"(d[1]), "+f"(d[2]), "+f"(d[3])
        : "r"(a[0]), "r"(a[1]), "r"(a[2]), "r"(a[3]), "r"(b0), "r"(b1));
}

// base = smem_weights + layer_off + lane*8. PASSES==3: hh+hl+lh; PASSES==1: hh.
template<int PASSES>
__device__ __forceinline__ void run_layer(const char* base,
        const uint32_t (&Ahi)[4][4], const uint32_t (&Alo)[4][4], float (&D)[8][4]) {
#pragma unroll
    for (int nt = 0; nt < 8; nt++) { D[nt][0] = 0.f; D[nt][1] = 0.f; D[nt][2] = 0.f; D[nt][3] = 0.f; }
#pragma unroll
    for (int kt = 0; kt < 4; kt++) {
#pragma unroll
        for (int nt = 0; nt < 8; nt++) {
            const char* p = base + (kt * 8 + nt) * 256;
            uint2 bh = *reinterpret_cast<const uint2*>(p);
            mma(D[nt], Ahi[kt], bh.x, bh.y);
            if (PASSES == 3) {
                uint2 bl = *reinterpret_cast<const uint2*>(p + 8192);
                mma(D[nt], Ahi[kt], bl.x, bl.y);
                mma(D[nt], Alo[kt], bh.x, bh.y);
            }
        }
    }
}

// att1: K=128 single-pass; kt 0..3 from Afjt (Ahi), kt 4..7 from Aq (reuses Alo regs)
__device__ __forceinline__ void run_att1(const char* base,
        const uint32_t (&Ahi)[4][4], const uint32_t (&Aq)[4][4], float (&D)[8][4]) {
#pragma unroll
    for (int nt = 0; nt < 8; nt++) { D[nt][0] = 0.f; D[nt][1] = 0.f; D[nt][2] = 0.f; D[nt][3] = 0.f; }
#pragma unroll
    for (int kt = 0; kt < 8; kt++) {
#pragma unroll
        for (int nt = 0; nt < 8; nt++) {
            const char* p = base + (kt * 8 + nt) * 256;
            uint2 bh = *reinterpret_cast<const uint2*>(p);
            mma(D[nt], (kt < 4) ? Ahi[kt] : Aq[kt - 4], bh.x, bh.y);
        }
    }
}

template<bool RELU, bool EX, bool SG, bool LO>
__device__ __forceinline__ void epilogue(float (&D)[8][4], uint32_t (&Ahi)[4][4], uint32_t (&Alo)[4][4],
        const float* bias, const float* e0, const float* e1, float* g0, float* g1, int tig) {
#pragma unroll
    for (int nt = 0; nt < 8; nt++) {
        int col = nt * 8 + 2 * tig;
        float2 bc = *reinterpret_cast<const float2*>(bias + col);
        float v0 = D[nt][0] + bc.x, v1 = D[nt][1] + bc.y;
        float v2 = D[nt][2] + bc.x, v3 = D[nt][3] + bc.y;
        if (EX) {
            float2 ea = *reinterpret_cast<const float2*>(e0 + col);
            float2 eb = *reinterpret_cast<const float2*>(e1 + col);
            v0 += ea.x; v1 += ea.y; v2 += eb.x; v3 += eb.y;
        }
        if (RELU) {
            v0 = fmaxf(v0, 0.f); v1 = fmaxf(v1, 0.f);
            v2 = fmaxf(v2, 0.f); v3 = fmaxf(v3, 0.f);
        }
        if (SG) {
            *reinterpret_cast<float2*>(g0 + col) = make_float2(v0, v1);
            *reinterpret_cast<float2*>(g1 + col) = make_float2(v2, v3);
        }
        int kt = nt >> 1, ix = (nt & 1) * 2;
        if (LO) {
            split2(v0, v1, Ahi[kt][ix],     Alo[kt][ix]);
            split2(v2, v3, Ahi[kt][ix + 1], Alo[kt][ix + 1]);
        } else {
            Ahi[kt][ix]     = cvt2(v0, v1);
            Ahi[kt][ix + 1] = cvt2(v2, v3);
        }
    }
}

// pack W[64xKT*16] (col-major B frags, hi and optionally lo)
__device__ __forceinline__ void pack_tile(char* dh, char* dl, const float* __restrict__ w,
                                          int KT, int tid) {
    for (int e = tid; e < KT * 256; e += THR) {
        int kt = e >> 8, rem = e & 255, nt = rem >> 5, th = rem & 31;
        int tg = th & 3, gn = th >> 2;
        int k0 = kt * 16 + tg * 2, n = nt * 8 + gn;
        uint32_t h0, l0, h1, l1;
        split2(w[k0 * 64 + n],       w[(k0 + 1) * 64 + n], h0, l0);
        split2(w[(k0 + 8) * 64 + n], w[(k0 + 9) * 64 + n], h1, l1);
        int off = (kt * 8 + nt) * 256 + th * 8;
        *reinterpret_cast<uint2*>(dh + off) = make_uint2(h0, h1);
        if (dl) *reinterpret_cast<uint2*>(dl + off) = make_uint2(l0, l1);
    }
}

// ===================== HMMA MLP kernel (no prep needed) =====================
__global__ void __launch_bounds__(THR, 2) mlp_mma_kernel(
    const int* __restrict__ nodes_v,
    const int* __restrict__ neigh_u, const int* __restrict__ neigh_r,
    const float* __restrict__ embed_u, const float* __restrict__ embed_i,
    const float* __restrict__ embed_r,
    const float* __restrict__ gv_w1, const float* __restrict__ gv_b1,
    const float* __restrict__ gv_w2, const float* __restrict__ gv_b2,
    const float* __restrict__ gv_w3, const float* __restrict__ gv_b3,
    const float* __restrict__ att_w1, const float* __restrict__ att_b1,
    const float* __restrict__ att_w2, const float* __restrict__ att_b2,
    const float* __restrict__ att_w3, const float* __restrict__ att_b3) {
    extern __shared__ char smem[];
    float* smf = reinterpret_cast<float*>(smem + FBASE);
    int tid = threadIdx.x;

    pack_tile(smem + L_GV1, smem + L_GV1 + 8192, gv_w1, 4, tid);   // pt half rows 0..63
    pack_tile(smem + L_GV2, smem + L_GV2 + 8192, gv_w2, 4, tid);
    pack_tile(smem + L_GV3, smem + L_GV3 + 8192, gv_w3, 4, tid);
    pack_tile(smem + L_ATT1, nullptr, att_w1, 8, tid);             // full K=128
    pack_tile(smem + L_ATT2, nullptr, att_w2, 4, tid);
    if (tid < 64) {
        smf[F_BG1 + tid] = gv_b1[tid];
        smf[F_BG2 + tid] = gv_b2[tid];
        smf[F_BG3 + tid] = gv_b3[tid];
        smf[F_BA1 + tid] = att_b1[tid];
        smf[F_BA2 + tid] = att_b2[tid];
        smf[F_W3 + tid]  = att_w3[tid];
    }
    // er_proj[r][j] = embed_r[r] @ gv_w1[64:128]  (NR=5)
    for (int e = tid; e < 320; e += THR) {
        int r = e >> 6, j = e & 63;
        float s = 0.f;
#pragma unroll 8
        for (int k = 0; k < 64; k++) s += embed_r[r * 64 + k] * gv_w1[(64 + k) * 64 + j];
        smf[F_ER + e] = s;
    }
    if (tid == 0) smf[F_BA3] = att_b3[0];
    __syncthreads();

    const char* ws = smem;
    int lane = tid & 31;
    int tig = lane & 3, gid = lane >> 2;
    int gw = blockIdx.x * (THR / 32) + (tid >> 5);
    int stride = gridDim.x * (THR / 32);
    int lb = lane * 8;

    uint32_t Ahi[4][4], Alo[4][4];
    float D[8][4];

    for (int t = gw; t < NT16; t += stride) {
        int grow0 = t * 16 + gid, grow1 = grow0 + 8;
        int nu0 = neigh_u[grow0], nu1 = neigh_u[grow1];
        int nr0 = neigh_r[grow0], nr1 = neigh_r[grow1];
        int b0 = (int)((unsigned)grow0 / 50u), b1 = (int)((unsigned)grow1 / 50u);

        const float* p0 = embed_u + (size_t)nu0 * 64 + 2 * tig;
        const float* p1 = embed_u + (size_t)nu1 * 64 + 2 * tig;
#pragma unroll
        for (int kt = 0; kt < 4; kt++) {
            float2 x0 = *reinterpret_cast<const float2*>(p0 + kt * 16);
            float2 x1 = *reinterpret_cast<const float2*>(p1 + kt * 16);
            float2 x2 = *reinterpret_cast<const float2*>(p0 + kt * 16 + 8);
            float2 x3 = *reinterpret_cast<const float2*>(p1 + kt * 16 + 8);
            split2(x0.x, x0.y, Ahi[kt][0], Alo[kt][0]);
            split2(x1.x, x1.y, Ahi[kt][1], Alo[kt][1]);
            split2(x2.x, x2.y, Ahi[kt][2], Alo[kt][2]);
            split2(x3.x, x3.y, Ahi[kt][3], Alo[kt][3]);
        }

        // L1-L3 full precision
        run_layer<3>(ws + L_GV1 + lb, Ahi, Alo, D);
        epilogue<true, true, false, true>(D, Ahi, Alo, smf + F_BG1,
                                          smf + F_ER + nr0 * 64, smf + F_ER + nr1 * 64,
                                          nullptr, nullptr, tig);
        run_layer<3>(ws + L_GV2 + lb, Ahi, Alo, D);
        epilogue<true, false, false, true>(D, Ahi, Alo, smf + F_BG2,
                                           nullptr, nullptr, nullptr, nullptr, tig);
        run_layer<3>(ws + L_GV3 + lb, Ahi, Alo, D);
        epilogue<false, false, true, false>(D, Ahi, Alo, smf + F_BG3,
                                            nullptr, nullptr,
                                            g_fjt + (size_t)grow0 * 64, g_fjt + (size_t)grow1 * 64, tig);

        // q fragments into Alo (dead after L3): rows b0/b1's item embedding
        {
            const float* q0 = embed_i + (size_t)nodes_v[b0] * 64 + 2 * tig;
            const float* q1 = embed_i + (size_t)nodes_v[b1] * 64 + 2 * tig;
#pragma unroll
            for (int kt = 0; kt < 4; kt++) {
                float2 x0 = *reinterpret_cast<const float2*>(q0 + kt * 16);
                float2 x1 = *reinterpret_cast<const float2*>(q1 + kt * 16);
                float2 x2 = *reinterpret_cast<const float2*>(q0 + kt * 16 + 8);
                float2 x3 = *reinterpret_cast<const float2*>(q1 + kt * 16 + 8);
                Alo[kt][0] = cvt2(x0.x, x0.y);
                Alo[kt][1] = cvt2(x1.x, x1.y);
                Alo[kt][2] = cvt2(x2.x, x2.y);
                Alo[kt][3] = cvt2(x3.x, x3.y);
            }
        }

        // L4: att1 K=128 single-pass
        run_att1(ws + L_ATT1 + lb, Ahi, Alo, D);
        epilogue<true, false, false, false>(D, Ahi, Alo, smf + F_BA1,
                                            nullptr, nullptr, nullptr, nullptr, tig);
        // L5: att2 single-pass + score dot
        run_layer<1>(ws + L_ATT2 + lb, Ahi, Alo, D);
        {
            float s0 = 0.f, s1 = 0.f;
            float ba3v = smf[F_BA3];
#pragma unroll
            for (int nt = 0; nt < 8; nt++) {
                int col = nt * 8 + 2 * tig;
                float2 bc = *reinterpret_cast<const float2*>(smf + F_BA2 + col);
                float2 wc = *reinterpret_cast<const float2*>(smf + F_W3 + col);
                s0 += fmaxf(D[nt][0] + bc.x, 0.f) * wc.x + fmaxf(D[nt][1] + bc.y, 0.f) * wc.y;
                s1 += fmaxf(D[nt][2] + bc.x, 0.f) * wc.x + fmaxf(D[nt][3] + bc.y, 0.f) * wc.y;
            }
            s0 += __shfl_xor_sync(0xffffffffu, s0, 1);
            s0 += __shfl_xor_sync(0xffffffffu, s0, 2);
            s1 += __shfl_xor_sync(0xffffffffu, s1, 1);
            s1 += __shfl_xor_sync(0xffffffffu, s1, 2);
            if (tig == 0) {
                g_scores[grow0] = s0 + ba3v;
                g_scores[grow1] = s1 + ba3v;
            }
        }
    }
}

// ===================== combine v3: warp-per-b, warp-synchronous =====================
__global__ void __launch_bounds__(256) combine_kernel(
    const int* __restrict__ nodes_v, const float* __restrict__ embed_i,
    const float* __restrict__ wr1_w, const float* __restrict__ wr1_b,
    const float* __restrict__ wr2_w, const float* __restrict__ wr2_b,
    float* __restrict__ out) {
    __shared__ float w1s[128 * 64];
    __shared__ float w2s[64 * 64];
    __shared__ float b1s[64], b2s[64];
    __shared__ float mus[8][64];
    __shared__ float zqs[8][128];
    __shared__ float zzs[8][64];

    int tid = threadIdx.x;
    int warp = tid >> 5, lane = tid & 31;

    for (int e = tid; e < 128 * 64; e += 256) w1s[e] = wr1_w[e];
    for (int e = tid; e < 64 * 64; e += 256) w2s[e] = wr2_w[e];
    if (tid < 64) { b1s[tid] = wr1_b[tid]; b2s[tid] = wr2_b[tid]; }
    __syncthreads();

    for (int b = blockIdx.x * 8 + warp; b < BB; b += gridDim.x * 8) {
        // softmax over 50 scores (lanes cover l and l+32)
        float s0 = (lane < LL) ? g_scores[b * LL + lane] : -1e30f;
        float s1 = (lane + 32 < LL) ? g_scores[b * LL + lane + 32] : -1e30f;
        float mx = fmaxf(s0, s1);
#pragma unroll
        for (int o = 16; o > 0; o >>= 1) mx = fmaxf(mx, __shfl_xor_sync(0xffffffffu, mx, o));
        float e0 = (lane < LL) ? __expf(s0 - mx) : 0.f;
        float e1 = (lane + 32 < LL) ? __expf(s1 - mx) : 0.f;
        float den = e0 + e1;
#pragma unroll
        for (int o = 16; o > 0; o >>= 1) den += __shfl_xor_sync(0xffffffffu, den, o);
        mus[warp][lane] = e0;
        mus[warp][lane + 32] = e1;
        __syncwarp();

        // zj[d] for d=lane, lane+32
        float a0 = 0.f, a1 = 0.f;
        const float* fb = g_fjt + (size_t)b * LL * 64;
#pragma unroll 10
        for (int l = 0; l < LL; l++) {
            float m = mus[warp][l];
            a0 += m * fb[l * 64 + lane];
            a1 += m * fb[l * 64 + lane + 32];
        }
        float inv = 1.f / den;
        zqs[warp][lane]      = a0 * inv;
        zqs[warp][lane + 32] = a1 * inv;
        const float* qi = embed_i + (size_t)nodes_v[b] * 64;
        zqs[warp][64 + lane]      = qi[lane];
        zqs[warp][96 + lane]      = qi[lane + 32];
        __syncwarp();

        // layer 1 (128 -> 64), relu
        float o0 = b1s[lane], o1 = b1s[lane + 32];
#pragma unroll 16
        for (int k = 0; k < 128; k++) {
            float v = zqs[warp][k];
            o0 += v * w1s[k * 64 + lane];
            o1 += v * w1s[k * 64 + lane + 32];
        }
        zzs[warp][lane]      = fmaxf(o0, 0.f);
        zzs[warp][lane + 32] = fmaxf(o1, 0.f);
        __syncwarp();

        // layer 2 (64 -> 64), relu
        float p0 = b2s[lane], p1 = b2s[lane + 32];
#pragma unroll 16
        for (int k = 0; k < 64; k++) {
            float v = zzs[warp][k];
            p0 += v * w2s[k * 64 + lane];
            p1 += v * w2s[k * 64 + lane + 32];
        }
        out[b * 64 + lane]      = fmaxf(p0, 0.f);
        out[b * 64 + lane + 32] = fmaxf(p1, 0.f);
        __syncwarp();
    }
}

extern "C" void kernel_launch(void* const* d_in, const int* in_sizes, int n_in,
                              void* d_out, int out_size) {
    const int*   nodes_v = (const int*)d_in[0];
    const int*   neigh_u = (const int*)d_in[1];
    const int*   neigh_r = (const int*)d_in[2];
    const float* embed_u = (const float*)d_in[3];
    const float* embed_i = (const float*)d_in[4];
    const float* embed_r = (const float*)d_in[5];
    const float* gv_w1  = (const float*)d_in[6];
    const float* gv_b1  = (const float*)d_in[7];
    const float* gv_w2  = (const float*)d_in[8];
    const float* gv_b2  = (const float*)d_in[9];
    const float* gv_w3  = (const float*)d_in[10];
    const float* gv_b3  = (const float*)d_in[11];
    const float* att_w1 = (const float*)d_in[12];
    const float* att_b1 = (const float*)d_in[13];
    const float* att_w2 = (const float*)d_in[14];
    const float* att_b2 = (const float*)d_in[15];
    const float* att_w3 = (const float*)d_in[16];
    const float* att_b3 = (const float*)d_in[17];
    const float* wr1_w  = (const float*)d_in[18];
    const float* wr1_b  = (const float*)d_in[19];
    const float* wr2_w  = (const float*)d_in[20];
    const float* wr2_b  = (const float*)d_in[21];
    float* out = (float*)d_out;

    cudaFuncSetAttribute(mlp_mma_kernel, cudaFuncAttributeMaxDynamicSharedMemorySize, SMEM_SZ);

    int smCount = 148;
    cudaDeviceGetAttribute(&smCount, cudaDevAttrMultiProcessorCount, 0);

    mlp_mma_kernel<<<2 * smCount, THR, SMEM_SZ>>>(
        nodes_v, neigh_u, neigh_r, embed_u, embed_i, embed_r,
        gv_w1, gv_b1, gv_w2, gv_b2, gv_w3, gv_b3,
        att_w1, att_b1, att_w2, att_b2, att_w3, att_b3);

    combine_kernel<<<128, 256>>>(nodes_v, embed_i, wr1_w, wr1_b, wr2_w, wr2_b, out);
}

// round 8
// speedup vs baseline: 1.2114x; 1.0654x over previous
#include <cuda_runtime.h>
#include <cuda_bf16.h>
#include <cstdint>
#include <math.h>

#define BB 4096
#define LL 50
#define DD 64

constexpr int ROWS_TOT = BB * LL;        // 204800
constexpr int NT16     = ROWS_TOT / 16;  // 12800 warp-tiles
constexpr int THR      = 256;

// ---- mlp smem layout (bytes) ----
constexpr int L_GV1  = 0;
constexpr int L_GV2  = 16384;
constexpr int L_GV3  = 32768;
constexpr int L_ATT1 = 49152;
constexpr int L_ATT2 = 65536;
constexpr int FBASE  = 73728;
constexpr int F_BG1 = 0, F_BG2 = 64, F_BG3 = 128, F_BA1 = 192, F_BA2 = 256;
constexpr int F_W3 = 320, F_BA3 = 384, F_ER = 448;
constexpr int SMEM_SZ = FBASE + 768 * 4;   // 76800 B

// device scratch
__device__ float g_scores[ROWS_TOT];
__device__ float g_fjt[ROWS_TOT * DD];

// ===================== helpers =====================
__device__ __forceinline__ uint32_t cvt2(float v_lo, float v_hi) {
    uint32_t r;
    asm("cvt.rn.bf16x2.f32 %0, %1, %2;" : "=r"(r) : "f"(v_hi), "f"(v_lo));
    return r;
}
__device__ __forceinline__ float blo(uint32_t p) { return __uint_as_float(p << 16); }
__device__ __forceinline__ float bhi(uint32_t p) { return __uint_as_float(p & 0xffff0000u); }
__device__ __forceinline__ void split2(float v0, float v1, uint32_t& h, uint32_t& l) {
    h = cvt2(v0, v1);
    l = cvt2(v0 - blo(h), v1 - bhi(h));
}
__device__ __forceinline__ void mma(float* d, const uint32_t* a, uint32_t b0, uint32_t b1) {
    asm volatile(
        "mma.sync.aligned.m16n8k16.row.col.f32.bf16.bf16.f32 "
        "{%0,%1,%2,%3}, {%4,%5,%6,%7}, {%8,%9}, {%0,%1,%2,%3};"
        : "+f"(d[0]), "+f"(d[1]), "+f"(d[2]), "+f"(d[3])
        : "r"(a[0]), "r"(a[1]), "r"(a[2]), "r"(a[3]), "r"(b0), "r"(b1));
}

template<int PASSES>
__device__ __forceinline__ void run_layer(const char* base,
        const uint32_t (&Ahi)[4][4], const uint32_t (&Alo)[4][4], float (&D)[8][4]) {
#pragma unroll
    for (int nt = 0; nt < 8; nt++) { D[nt][0] = 0.f; D[nt][1] = 0.f; D[nt][2] = 0.f; D[nt][3] = 0.f; }
#pragma unroll
    for (int kt = 0; kt < 4; kt++) {
#pragma unroll
        for (int nt = 0; nt < 8; nt++) {
            const char* p = base + (kt * 8 + nt) * 256;
            uint2 bh = *reinterpret_cast<const uint2*>(p);
            mma(D[nt], Ahi[kt], bh.x, bh.y);
            if (PASSES == 3) {
                uint2 bl = *reinterpret_cast<const uint2*>(p + 8192);
                mma(D[nt], Ahi[kt], bl.x, bl.y);
                mma(D[nt], Alo[kt], bh.x, bh.y);
            }
        }
    }
}

__device__ __forceinline__ void run_att1(const char* base,
        const uint32_t (&Ahi)[4][4], const uint32_t (&Aq)[4][4], float (&D)[8][4]) {
#pragma unroll
    for (int nt = 0; nt < 8; nt++) { D[nt][0] = 0.f; D[nt][1] = 0.f; D[nt][2] = 0.f; D[nt][3] = 0.f; }
#pragma unroll
    for (int kt = 0; kt < 8; kt++) {
#pragma unroll
        for (int nt = 0; nt < 8; nt++) {
            const char* p = base + (kt * 8 + nt) * 256;
            uint2 bh = *reinterpret_cast<const uint2*>(p);
            mma(D[nt], (kt < 4) ? Ahi[kt] : Aq[kt - 4], bh.x, bh.y);
        }
    }
}

template<bool RELU, bool EX, bool SG, bool LO>
__device__ __forceinline__ void epilogue(float (&D)[8][4], uint32_t (&Ahi)[4][4], uint32_t (&Alo)[4][4],
        const float* bias, const float* e0, const float* e1, float* g0, float* g1, int tig) {
#pragma unroll
    for (int nt = 0; nt < 8; nt++) {
        int col = nt * 8 + 2 * tig;
        float2 bc = *reinterpret_cast<const float2*>(bias + col);
        float v0 = D[nt][0] + bc.x, v1 = D[nt][1] + bc.y;
        float v2 = D[nt][2] + bc.x, v3 = D[nt][3] + bc.y;
        if (EX) {
            float2 ea = *reinterpret_cast<const float2*>(e0 + col);
            float2 eb = *reinterpret_cast<const float2*>(e1 + col);
            v0 += ea.x; v1 += ea.y; v2 += eb.x; v3 += eb.y;
        }
        if (RELU) {
            v0 = fmaxf(v0, 0.f); v1 = fmaxf(v1, 0.f);
            v2 = fmaxf(v2, 0.f); v3 = fmaxf(v3, 0.f);
        }
        if (SG) {
            *reinterpret_cast<float2*>(g0 + col) = make_float2(v0, v1);
            *reinterpret_cast<float2*>(g1 + col) = make_float2(v2, v3);
        }
        int kt = nt >> 1, ix = (nt & 1) * 2;
        if (LO) {
            split2(v0, v1, Ahi[kt][ix],     Alo[kt][ix]);
            split2(v2, v3, Ahi[kt][ix + 1], Alo[kt][ix + 1]);
        } else {
            Ahi[kt][ix]     = cvt2(v0, v1);
            Ahi[kt][ix + 1] = cvt2(v2, v3);
        }
    }
}

__device__ __forceinline__ void pack_tile(char* dh, char* dl, const float* __restrict__ w,
                                          int KT, int tid) {
    for (int e = tid; e < KT * 256; e += THR) {
        int kt = e >> 8, rem = e & 255, nt = rem >> 5, th = rem & 31;
        int tg = th & 3, gn = th >> 2;
        int k0 = kt * 16 + tg * 2, n = nt * 8 + gn;
        uint32_t h0, l0, h1, l1;
        split2(w[k0 * 64 + n],       w[(k0 + 1) * 64 + n], h0, l0);
        split2(w[(k0 + 8) * 64 + n], w[(k0 + 9) * 64 + n], h1, l1);
        int off = (kt * 8 + nt) * 256 + th * 8;
        *reinterpret_cast<uint2*>(dh + off) = make_uint2(h0, h1);
        if (dl) *reinterpret_cast<uint2*>(dl + off) = make_uint2(l0, l1);
    }
}

// ===================== HMMA MLP kernel =====================
__global__ void __launch_bounds__(THR, 2) mlp_mma_kernel(
    const int* __restrict__ nodes_v,
    const int* __restrict__ neigh_u, const int* __restrict__ neigh_r,
    const float* __restrict__ embed_u, const float* __restrict__ embed_i,
    const float* __restrict__ embed_r,
    const float* __restrict__ gv_w1, const float* __restrict__ gv_b1,
    const float* __restrict__ gv_w2, const float* __restrict__ gv_b2,
    const float* __restrict__ gv_w3, const float* __restrict__ gv_b3,
    const float* __restrict__ att_w1, const float* __restrict__ att_b1,
    const float* __restrict__ att_w2, const float* __restrict__ att_b2,
    const float* __restrict__ att_w3, const float* __restrict__ att_b3) {
    extern __shared__ char smem[];
    float* smf = reinterpret_cast<float*>(smem + FBASE);
    int tid = threadIdx.x;

    pack_tile(smem + L_GV1, smem + L_GV1 + 8192, gv_w1, 4, tid);
    pack_tile(smem + L_GV2, smem + L_GV2 + 8192, gv_w2, 4, tid);
    pack_tile(smem + L_GV3, smem + L_GV3 + 8192, gv_w3, 4, tid);
    pack_tile(smem + L_ATT1, nullptr, att_w1, 8, tid);
    pack_tile(smem + L_ATT2, nullptr, att_w2, 4, tid);
    if (tid < 64) {
        smf[F_BG1 + tid] = gv_b1[tid];
        smf[F_BG2 + tid] = gv_b2[tid];
        smf[F_BG3 + tid] = gv_b3[tid];
        smf[F_BA1 + tid] = att_b1[tid];
        smf[F_BA2 + tid] = att_b2[tid];
        smf[F_W3 + tid]  = att_w3[tid];
    }
    for (int e = tid; e < 320; e += THR) {
        int r = e >> 6, j = e & 63;
        float s = 0.f;
#pragma unroll 8
        for (int k = 0; k < 64; k++) s += embed_r[r * 64 + k] * gv_w1[(64 + k) * 64 + j];
        smf[F_ER + e] = s;
    }
    if (tid == 0) smf[F_BA3] = att_b3[0];
    __syncthreads();

    const char* ws = smem;
    int lane = tid & 31;
    int tig = lane & 3, gid = lane >> 2;
    int gw = blockIdx.x * (THR / 32) + (tid >> 5);
    int stride = gridDim.x * (THR / 32);
    int lb = lane * 8;

    uint32_t Ahi[4][4], Alo[4][4];
    float D[8][4];

    for (int t = gw; t < NT16; t += stride) {
        int grow0 = t * 16 + gid, grow1 = grow0 + 8;
        int nu0 = neigh_u[grow0], nu1 = neigh_u[grow1];
        int nr0 = neigh_r[grow0], nr1 = neigh_r[grow1];
        int b0 = (int)((unsigned)grow0 / 50u), b1 = (int)((unsigned)grow1 / 50u);

        const float* p0 = embed_u + (size_t)nu0 * 64 + 2 * tig;
        const float* p1 = embed_u + (size_t)nu1 * 64 + 2 * tig;
#pragma unroll
        for (int kt = 0; kt < 4; kt++) {
            float2 x0 = *reinterpret_cast<const float2*>(p0 + kt * 16);
            float2 x1 = *reinterpret_cast<const float2*>(p1 + kt * 16);
            float2 x2 = *reinterpret_cast<const float2*>(p0 + kt * 16 + 8);
            float2 x3 = *reinterpret_cast<const float2*>(p1 + kt * 16 + 8);
            split2(x0.x, x0.y, Ahi[kt][0], Alo[kt][0]);
            split2(x1.x, x1.y, Ahi[kt][1], Alo[kt][1]);
            split2(x2.x, x2.y, Ahi[kt][2], Alo[kt][2]);
            split2(x3.x, x3.y, Ahi[kt][3], Alo[kt][3]);
        }

        run_layer<3>(ws + L_GV1 + lb, Ahi, Alo, D);
        epilogue<true, true, false, true>(D, Ahi, Alo, smf + F_BG1,
                                          smf + F_ER + nr0 * 64, smf + F_ER + nr1 * 64,
                                          nullptr, nullptr, tig);
        run_layer<3>(ws + L_GV2 + lb, Ahi, Alo, D);
        epilogue<true, false, false, true>(D, Ahi, Alo, smf + F_BG2,
                                           nullptr, nullptr, nullptr, nullptr, tig);
        run_layer<3>(ws + L_GV3 + lb, Ahi, Alo, D);
        epilogue<false, false, true, false>(D, Ahi, Alo, smf + F_BG3,
                                            nullptr, nullptr,
                                            g_fjt + (size_t)grow0 * 64, g_fjt + (size_t)grow1 * 64, tig);

        {
            const float* q0 = embed_i + (size_t)nodes_v[b0] * 64 + 2 * tig;
            const float* q1 = embed_i + (size_t)nodes_v[b1] * 64 + 2 * tig;
#pragma unroll
            for (int kt = 0; kt < 4; kt++) {
                float2 x0 = *reinterpret_cast<const float2*>(q0 + kt * 16);
                float2 x1 = *reinterpret_cast<const float2*>(q1 + kt * 16);
                float2 x2 = *reinterpret_cast<const float2*>(q0 + kt * 16 + 8);
                float2 x3 = *reinterpret_cast<const float2*>(q1 + kt * 16 + 8);
                Alo[kt][0] = cvt2(x0.x, x0.y);
                Alo[kt][1] = cvt2(x1.x, x1.y);
                Alo[kt][2] = cvt2(x2.x, x2.y);
                Alo[kt][3] = cvt2(x3.x, x3.y);
            }
        }

        run_att1(ws + L_ATT1 + lb, Ahi, Alo, D);
        epilogue<true, false, false, false>(D, Ahi, Alo, smf + F_BA1,
                                            nullptr, nullptr, nullptr, nullptr, tig);
        run_layer<1>(ws + L_ATT2 + lb, Ahi, Alo, D);
        {
            float s0 = 0.f, s1 = 0.f;
            float ba3v = smf[F_BA3];
#pragma unroll
            for (int nt = 0; nt < 8; nt++) {
                int col = nt * 8 + 2 * tig;
                float2 bc = *reinterpret_cast<const float2*>(smf + F_BA2 + col);
                float2 wc = *reinterpret_cast<const float2*>(smf + F_W3 + col);
                s0 += fmaxf(D[nt][0] + bc.x, 0.f) * wc.x + fmaxf(D[nt][1] + bc.y, 0.f) * wc.y;
                s1 += fmaxf(D[nt][2] + bc.x, 0.f) * wc.x + fmaxf(D[nt][3] + bc.y, 0.f) * wc.y;
            }
            s0 += __shfl_xor_sync(0xffffffffu, s0, 1);
            s0 += __shfl_xor_sync(0xffffffffu, s0, 2);
            s1 += __shfl_xor_sync(0xffffffffu, s1, 1);
            s1 += __shfl_xor_sync(0xffffffffu, s1, 2);
            if (tig == 0) {
                g_scores[grow0] = s0 + ba3v;
                g_scores[grow1] = s1 + ba3v;
            }
        }
    }
}

// ===================== combine v4: warp-per-b, 512 blocks =====================
__global__ void __launch_bounds__(256) combine_kernel(
    const int* __restrict__ nodes_v, const float* __restrict__ embed_i,
    const float* __restrict__ wr1_w, const float* __restrict__ wr1_b,
    const float* __restrict__ wr2_w, const float* __restrict__ wr2_b,
    float* __restrict__ out) {
    __shared__ float w1s[128 * 64];
    __shared__ float w2s[64 * 64];
    __shared__ float b1s[64], b2s[64];
    __shared__ float mus[8][64];
    __shared__ float zqs[8][128];
    __shared__ float zzs[8][64];

    int tid = threadIdx.x;
    int warp = tid >> 5, lane = tid & 31;

    // stage weights via float4
    {
        const float4* s1 = reinterpret_cast<const float4*>(wr1_w);
        float4* d1 = reinterpret_cast<float4*>(w1s);
        for (int e = tid; e < 128 * 16; e += 256) d1[e] = s1[e];
        const float4* s2 = reinterpret_cast<const float4*>(wr2_w);
        float4* d2 = reinterpret_cast<float4*>(w2s);
        for (int e = tid; e < 64 * 16; e += 256) d2[e] = s2[e];
        if (tid < 64) { b1s[tid] = wr1_b[tid]; b2s[tid] = wr2_b[tid]; }
    }
    __syncthreads();

    int b = blockIdx.x * 8 + warp;
    if (b < BB) {
        // softmax over 50 scores
        float s0 = (lane < LL) ? g_scores[b * LL + lane] : -1e30f;
        float s1 = (lane + 32 < LL) ? g_scores[b * LL + lane + 32] : -1e30f;
        float mx = fmaxf(s0, s1);
#pragma unroll
        for (int o = 16; o > 0; o >>= 1) mx = fmaxf(mx, __shfl_xor_sync(0xffffffffu, mx, o));
        float e0 = (lane < LL) ? __expf(s0 - mx) : 0.f;
        float e1 = (lane + 32 < LL) ? __expf(s1 - mx) : 0.f;
        float den = e0 + e1;
#pragma unroll
        for (int o = 16; o > 0; o >>= 1) den += __shfl_xor_sync(0xffffffffu, den, o);
        mus[warp][lane] = e0;
        mus[warp][lane + 32] = e1;
        __syncwarp();

        float a0 = 0.f, a1 = 0.f;
        const float* fb = g_fjt + (size_t)b * LL * 64;
#pragma unroll 10
        for (int l = 0; l < LL; l++) {
            float m = mus[warp][l];
            a0 += m * fb[l * 64 + lane];
            a1 += m * fb[l * 64 + lane + 32];
        }
        float inv = 1.f / den;
        zqs[warp][lane]      = a0 * inv;
        zqs[warp][lane + 32] = a1 * inv;
        const float* qi = embed_i + (size_t)nodes_v[b] * 64;
        zqs[warp][64 + lane] = qi[lane];
        zqs[warp][96 + lane] = qi[lane + 32];
        __syncwarp();

        float o0 = b1s[lane], o1 = b1s[lane + 32];
#pragma unroll 16
        for (int k = 0; k < 128; k++) {
            float v = zqs[warp][k];
            o0 += v * w1s[k * 64 + lane];
            o1 += v * w1s[k * 64 + lane + 32];
        }
        zzs[warp][lane]      = fmaxf(o0, 0.f);
        zzs[warp][lane + 32] = fmaxf(o1, 0.f);
        __syncwarp();

        float p0 = b2s[lane], p1 = b2s[lane + 32];
#pragma unroll 16
        for (int k = 0; k < 64; k++) {
            float v = zzs[warp][k];
            p0 += v * w2s[k * 64 + lane];
            p1 += v * w2s[k * 64 + lane + 32];
        }
        out[b * 64 + lane]      = fmaxf(p0, 0.f);
        out[b * 64 + lane + 32] = fmaxf(p1, 0.f);
    }
}

extern "C" void kernel_launch(void* const* d_in, const int* in_sizes, int n_in,
                              void* d_out, int out_size) {
    const int*   nodes_v = (const int*)d_in[0];
    const int*   neigh_u = (const int*)d_in[1];
    const int*   neigh_r = (const int*)d_in[2];
    const float* embed_u = (const float*)d_in[3];
    const float* embed_i = (const float*)d_in[4];
    const float* embed_r = (const float*)d_in[5];
    const float* gv_w1  = (const float*)d_in[6];
    const float* gv_b1  = (const float*)d_in[7];
    const float* gv_w2  = (const float*)d_in[8];
    const float* gv_b2  = (const float*)d_in[9];
    const float* gv_w3  = (const float*)d_in[10];
    const float* gv_b3  = (const float*)d_in[11];
    const float* att_w1 = (const float*)d_in[12];
    const float* att_b1 = (const float*)d_in[13];
    const float* att_w2 = (const float*)d_in[14];
    const float* att_b2 = (const float*)d_in[15];
    const float* att_w3 = (const float*)d_in[16];
    const float* att_b3 = (const float*)d_in[17];
    const float* wr1_w  = (const float*)d_in[18];
    const float* wr1_b  = (const float*)d_in[19];
    const float* wr2_w  = (const float*)d_in[20];
    const float* wr2_b  = (const float*)d_in[21];
    float* out = (float*)d_out;

    cudaFuncSetAttribute(mlp_mma_kernel, cudaFuncAttributeMaxDynamicSharedMemorySize, SMEM_SZ);

    int smCount = 148;
    cudaDeviceGetAttribute(&smCount, cudaDevAttrMultiProcessorCount, 0);

    mlp_mma_kernel<<<2 * smCount, THR, SMEM_SZ>>>(
        nodes_v, neigh_u, neigh_r, embed_u, embed_i, embed_r,
        gv_w1, gv_b1, gv_w2, gv_b2, gv_w3, gv_b3,
        att_w1, att_b1, att_w2, att_b2, att_w3, att_b3);

    combine_kernel<<<BB / 8, 256>>>(nodes_v, embed_i, wr1_w, wr1_b, wr2_w, wr2_b, out);
}